// round 8
// baseline (speedup 1.0000x reference)
#include <cuda_runtime.h>
#include <cuda_fp16.h>
#include <cstdint>

// TALayer = 9-tap conv, tap offsets d_j = 16*(j/3)+(j%3)-17.
// GEMM: D[o,t] = sum_k W[o,k]*X[k,t], k=(j,c), K=576.
// fp16 m16n8k16, B frags via ldmatrix.x4 from t-major smem.
// 2 CTAs/SM x 256 thr; warp tile = 32o x 64t; T_TILE=256.

#define T_LEN  65536
#define NO     64
#define NC     64
#define T_TILE 256
#define HALO   17
#define XROWS  (T_TILE + 2*HALO)   // 290
#define XSTH   72                  // halves per x row (144B: 16B-aligned, bank-clean)
#define NCHUNK 36                  // K=576 / 16
#define GRID   296                 // 2 CTAs/SM * 148
#define NTILES 2048                // 8 * 65536/256

// smem byte offsets
#define WFOFF   0
#define WFBYTES (NCHUNK*4*32*16)        // 73728: [chunk][mt(4)][lane]{a0..a3}
#define XSOFF   WFBYTES
#define XSBYTES (XROWS*XSTH*2)          // 41760
#define SMTOT   (XSOFF + XSBYTES)       // 115488

// W fragments, exact m16n8k16 f16 A-frag layout.
__device__ uint32_t g_wfrag[NCHUNK*4*32*4];

__device__ __forceinline__ uint32_t packh2(float lo, float hi) {
    __half2 h = __floats2half2_rn(lo, hi);
    return *(uint32_t*)&h;
}

__global__ void prep_w(const float* __restrict__ w) {
    int tid = blockIdx.x * blockDim.x + threadIdx.x;
    if (tid >= NCHUNK * 128) return;
    int q = tid >> 7, r = tid & 127, mt = r >> 5, lane = r & 31;
    int j = q >> 2, cq = q & 3;
    int o0 = mt * 16 + (lane >> 2);
    int c0 = cq * 16 + (lane & 3) * 2;
    uint4 u;
    u.x = packh2(w[o0*576 + c0*9 + j],        w[o0*576 + (c0+1)*9 + j]);
    u.y = packh2(w[(o0+8)*576 + c0*9 + j],    w[(o0+8)*576 + (c0+1)*9 + j]);
    u.z = packh2(w[o0*576 + (c0+8)*9 + j],    w[o0*576 + (c0+9)*9 + j]);
    u.w = packh2(w[(o0+8)*576 + (c0+8)*9 + j],w[(o0+8)*576 + (c0+9)*9 + j]);
    ((uint4*)g_wfrag)[tid] = u;
}

extern __shared__ char sm[];

__device__ __forceinline__ uint32_t s2u(const void* p) {
    uint32_t a;
    asm("{ .reg .u64 t; cvta.to.shared.u64 t, %1; cvt.u32.u64 %0, t; }"
        : "=r"(a) : "l"(p));
    return a;
}

__global__ __launch_bounds__(256, 2) void taconv_mma(
    const float* __restrict__ x, const float* __restrict__ bias,
    float* __restrict__ out)
{
    const int tid  = threadIdx.x;
    const int wid  = tid >> 5;
    const int lane = tid & 31;
    const int og   = wid & 1;        // o-half: 2 mtiles of 16
    const int tg   = wid >> 1;       // t-group: 64 time steps (4 groups)

    // ---- stage W fragments into smem (once) ----
    {
        const uint4* gw = (const uint4*)g_wfrag;
        uint4* sw = (uint4*)(sm + WFOFF);
        for (int i = tid; i < NCHUNK * 128; i += 256) sw[i] = gw[i];
    }

    // bias regs (warp o-assignment is tile-invariant)
    const int oA0 = og * 32 + (lane >> 2);
    float bv[2][2];
#pragma unroll
    for (int m = 0; m < 2; ++m) {
        bv[m][0] = __ldg(bias + oA0 + m * 16);
        bv[m][1] = __ldg(bias + oA0 + m * 16 + 8);
    }

    // ldmatrix per-lane base: row t = tg*64 + p*32 + lane (p in addr step)
    const uint32_t xsu = s2u(sm + XSOFF);
    const uint32_t ldm_base = xsu + (uint32_t)(tg * 64 + lane) * (XSTH * 2);

    for (int tile = blockIdx.x; tile < NTILES; tile += GRID) {
        const int b  = tile >> 8;
        const int t0 = (tile & 255) << 8;

        __syncthreads();   // xs safe to overwrite (also orders W staging, iter 0)

        // ---- x tile -> smem as fp16, t-major: xs[i][c] ----
        const float* xb = x + (size_t)b * NC * T_LEN;
        __half* xsh = (__half*)(sm + XSOFF);
#pragma unroll 5
        for (int it = 0; it < 73; ++it) {
            int idx = it * 256 + tid;              // idx = c*290 + i
            if (idx < NC * XROWS) {
                int c = idx / XROWS, i = idx - c * XROWS;
                int g = t0 - HALO + i;
                float v = (g >= 0 && g < T_LEN)
                        ? __ldg(xb + (size_t)c * T_LEN + g) : 0.0f;
                xsh[i * XSTH + c] = __float2half_rn(v);
            }
        }
        __syncthreads();

        // ---- mainloop: 36 K-chunks (k=16), 16 mma each ----
        float acc[2][8][4];
#pragma unroll
        for (int m = 0; m < 2; ++m)
#pragma unroll
            for (int n = 0; n < 8; ++n)
#pragma unroll
                for (int r = 0; r < 4; ++r) acc[m][n][r] = 0.0f;

        const uint4* wf_base = (const uint4*)(sm + WFOFF);

#pragma unroll
        for (int j = 0; j < 9; ++j) {
            const int offj = 16 * (j / 3) + (j % 3);   // d_j + HALO
#pragma unroll
            for (int cq = 0; cq < 4; ++cq) {
                const int q = j * 4 + cq;
                uint4 wf[2];
#pragma unroll
                for (int m = 0; m < 2; ++m)
                    wf[m] = wf_base[(q * 4 + og * 2 + m) * 32 + lane];

                // B frags: bb[nt] = {b0 (kg=0), b1 (kg=1)}, nt = p*4 + reg
                uint32_t bb[8][2];
                const uint32_t abase =
                    ldm_base + (uint32_t)(offj * (XSTH * 2) + cq * 32);
#pragma unroll
                for (int p = 0; p < 2; ++p) {
#pragma unroll
                    for (int kg = 0; kg < 2; ++kg) {
                        uint32_t a = abase + p * (32 * XSTH * 2) + kg * 16;
                        asm volatile(
                            "ldmatrix.sync.aligned.m8n8.x4.shared.b16 "
                            "{%0,%1,%2,%3}, [%4];"
                            : "=r"(bb[p*4+0][kg]), "=r"(bb[p*4+1][kg]),
                              "=r"(bb[p*4+2][kg]), "=r"(bb[p*4+3][kg])
                            : "r"(a));
                    }
                }
#pragma unroll
                for (int m = 0; m < 2; ++m)
#pragma unroll
                    for (int nt = 0; nt < 8; ++nt)
                        asm volatile(
                            "mma.sync.aligned.m16n8k16.row.col.f32.f16.f16.f32 "
                            "{%0,%1,%2,%3}, {%4,%5,%6,%7}, {%8,%9}, {%0,%1,%2,%3};"
                            : "+f"(acc[m][nt][0]), "+f"(acc[m][nt][1]),
                              "+f"(acc[m][nt][2]), "+f"(acc[m][nt][3])
                            : "r"(wf[m].x), "r"(wf[m].y),
                              "r"(wf[m].z), "r"(wf[m].w),
                              "r"(bb[nt][0]), "r"(bb[nt][1]));
            }
        }

        // ---- epilogue: +bias, STG.64 per C-fragment pair ----
        float* ob = out + (size_t)b * NO * T_LEN + t0 + tg * 64 + 2 * (lane & 3);
#pragma unroll
        for (int m = 0; m < 2; ++m) {
            int oA = oA0 + m * 16;
#pragma unroll
            for (int nt = 0; nt < 8; ++nt) {
                float2 v0 = make_float2(acc[m][nt][0] + bv[m][0],
                                        acc[m][nt][1] + bv[m][0]);
                float2 v1 = make_float2(acc[m][nt][2] + bv[m][1],
                                        acc[m][nt][3] + bv[m][1]);
                *(float2*)(ob + (size_t)oA * T_LEN + nt * 8) = v0;
                *(float2*)(ob + (size_t)(oA + 8) * T_LEN + nt * 8) = v1;
            }
        }
    }
}

extern "C" void kernel_launch(void* const* d_in, const int* in_sizes, int n_in,
                              void* d_out, int out_size) {
    const float* x    = (const float*)d_in[0];
    const float* w    = (const float*)d_in[1];
    const float* bias = (const float*)d_in[2];
    float* out = (float*)d_out;

    prep_w<<<(NCHUNK * 128 + 255) / 256, 256>>>(w);

    cudaFuncSetAttribute(taconv_mma,
                         cudaFuncAttributeMaxDynamicSharedMemorySize, SMTOT);
    taconv_mma<<<GRID, 256, SMTOT>>>(x, bias, out);
}

// round 9
// speedup vs baseline: 2.1876x; 2.1876x over previous
#include <cuda_runtime.h>
#include <cuda_fp16.h>
#include <cstdint>

// TALayer = 9-tap conv, tap offsets d_j = 16*(j/3)+(j%3)-17.
// GEMM: D[o,t] = sum_k W[o,k]*X[k,t], k=(j,c), K=576.
// fp16 m16n8k16. x pre-converted to fp16 in t-major padded layout g_xt,
// staged per tile via double-buffered cp.async. 1 CTA/SM x 512 thr,
// warp tile = 32o x 32t, T_TILE = 256.

#define T_LEN   65536
#define TP      65600        // 32 pad + 65536 + 32 pad (t rows per b)
#define NB      8
#define NO      64
#define NC      64
#define T_TILE  256
#define HALO    17
#define XROWS   290          // T_TILE + 2*HALO
#define XPW     36           // words per smem x row (144B, bank-clean)
#define NCHUNK  36           // K=576/16
#define GRID    148
#define NTILES  2048         // NB * T_LEN/T_TILE

// smem byte offsets
#define WFOFF   0
#define WFBYTES (NCHUNK*4*32*16)     // 73728
#define XS0     WFBYTES
#define XBUFB   (XROWS*XPW*4)        // 41760
#define XS1     (XS0 + XBUFB)
#define SMTOT   (XS1 + XBUFB)        // 157248

// W fragments, exact m16n8k16 f16 A-frag layout.
__device__ uint32_t g_wfrag[NCHUNK*4*32*4];
// x as fp16, layout [b][t+32][c] (rows of 64 halves = 128B), pads zeroed.
__device__ __align__(16) __half g_xt[(size_t)NB * TP * NC];

__device__ __forceinline__ uint32_t packh2(float lo, float hi) {
    __half2 h = __floats2half2_rn(lo, hi);
    return *(uint32_t*)&h;
}

__global__ void prep_w(const float* __restrict__ w) {
    int tid = blockIdx.x * blockDim.x + threadIdx.x;
    if (tid >= NCHUNK * 128) return;
    int q = tid >> 7, r = tid & 127, mt = r >> 5, lane = r & 31;
    int j = q >> 2, cq = q & 3;
    int o0 = mt * 16 + (lane >> 2);
    int c0 = cq * 16 + (lane & 3) * 2;
    uint4 u;
    u.x = packh2(w[o0*576 + c0*9 + j],        w[o0*576 + (c0+1)*9 + j]);
    u.y = packh2(w[(o0+8)*576 + c0*9 + j],    w[(o0+8)*576 + (c0+1)*9 + j]);
    u.z = packh2(w[o0*576 + (c0+8)*9 + j],    w[o0*576 + (c0+9)*9 + j]);
    u.w = packh2(w[(o0+8)*576 + (c0+8)*9 + j],w[(o0+8)*576 + (c0+9)*9 + j]);
    ((uint4*)g_wfrag)[tid] = u;
}

// Transpose + convert: x[b][c][t] f32 -> g_xt[b][32+t][c] fp16.
__global__ void conv_x(const float* __restrict__ x) {
    __shared__ __half tile[256][66];    // pad 66: conflict-free both phases
    int b  = blockIdx.x >> 8;
    int t0 = (blockIdx.x & 255) << 8;
    int tid = threadIdx.x;
#pragma unroll 8
    for (int c = 0; c < 64; ++c)
        tile[tid][c] = __float2half_rn(x[((size_t)(b*64 + c))*T_LEN + t0 + tid]);
    __syncthreads();
    uint32_t* dst = (uint32_t*)g_xt;
#pragma unroll 8
    for (int it = 0; it < 32; ++it) {
        int idx = it * 256 + tid;
        int i = idx >> 5, w = idx & 31;
        __half2 h2;
        h2.x = tile[i][2*w]; h2.y = tile[i][2*w + 1];
        dst[((size_t)b*TP + 32 + t0 + i)*32 + w] = *(uint32_t*)&h2;
    }
}

__global__ void zero_pads() {
    int tid = blockIdx.x * 256 + threadIdx.x;   // NB * 64 rows * 32 words
    if (tid >= NB * 64 * 32) return;
    int b = tid / (64*32), r = (tid >> 5) & 63, w = tid & 31;
    int tp = (r < 32) ? r : (TP - 64 + r);
    ((uint32_t*)g_xt)[((size_t)b*TP + tp)*32 + w] = 0;
}

extern __shared__ char sm[];

__device__ __forceinline__ uint32_t s2u(const void* p) {
    uint32_t a;
    asm("{ .reg .u64 t; cvta.to.shared.u64 t, %1; cvt.u32.u64 %0, t; }"
        : "=r"(a) : "l"(p));
    return a;
}

#define CP_ASYNC16(d, s) \
    asm volatile("cp.async.cg.shared.global [%0], [%1], 16;" :: "r"(d), "l"(s))
#define CP_COMMIT() asm volatile("cp.async.commit_group;" ::: "memory")
#define CP_WAIT0()  asm volatile("cp.async.wait_group 0;" ::: "memory")

// Stage one tile's x rows (290 x 128B) into smem buffer via cp.async.
__device__ __forceinline__ void stage_x(int tile, uint32_t dstu, int tid) {
    const int b  = tile >> 8;
    const int t0 = (tile & 255) << 8;
    const char* src = (const char*)(g_xt + ((size_t)b*TP + 15 + t0) * 64);
#pragma unroll
    for (int s = 0; s < 5; ++s) {
        int idx = s * 512 + tid;
        if (idx < XROWS * 8) {
            int r = idx >> 3, ch = idx & 7;
            CP_ASYNC16(dstu + r*(XPW*4) + ch*16, src + (size_t)r*128 + ch*16);
        }
    }
}

__global__ __launch_bounds__(512, 1) void taconv_mma(
    const float* __restrict__ bias, float* __restrict__ out)
{
    const int tid  = threadIdx.x;
    const int wid  = tid >> 5;
    const int lane = tid & 31;
    const int og   = wid & 1;        // o-half: 2 mtiles of 16
    const int tg   = wid >> 1;       // t-group: 32 t each (8 groups)

    // ---- stage W fragments into smem (once) ----
    {
        const uint4* gw = (const uint4*)g_wfrag;
        uint4* sw = (uint4*)(sm + WFOFF);
        for (int i = tid; i < NCHUNK * 128; i += 512) sw[i] = gw[i];
    }
    const int oA0 = og * 32 + (lane >> 2);
    float bv[2][2];
#pragma unroll
    for (int m = 0; m < 2; ++m) {
        bv[m][0] = __ldg(bias + oA0 + m * 16);
        bv[m][1] = __ldg(bias + oA0 + m * 16 + 8);
    }

    const uint32_t smb = s2u(sm);
    const int wrow = tg * 32 + (lane >> 2);   // B-frag t-row base (pre-shift)

    int tile = blockIdx.x;
    stage_x(tile, smb + XS0, tid);
    CP_COMMIT();

    for (int it = 0; tile < NTILES; tile += GRID, ++it) {
        CP_WAIT0();
        __syncthreads();

        // overlap: prefetch next tile into the other buffer
        if (tile + GRID < NTILES)
            stage_x(tile + GRID, smb + ((it & 1) ? XS0 : XS1), tid);
        CP_COMMIT();

        const uint32_t* xs =
            (const uint32_t*)(sm + ((it & 1) ? XS1 : XS0));
        const uint4* wf_base = (const uint4*)(sm + WFOFF);

        float acc[2][4][4];
#pragma unroll
        for (int m = 0; m < 2; ++m)
#pragma unroll
            for (int n = 0; n < 4; ++n)
#pragma unroll
                for (int r = 0; r < 4; ++r) acc[m][n][r] = 0.0f;

#pragma unroll
        for (int j = 0; j < 9; ++j) {
            const int offj = 16 * (j / 3) + (j % 3);   // d_j + HALO
#pragma unroll
            for (int cq = 0; cq < 4; ++cq) {
                const int q = j * 4 + cq;
                uint4 wf[2];
#pragma unroll
                for (int m = 0; m < 2; ++m)
                    wf[m] = wf_base[(q * 4 + og * 2 + m) * 32 + lane];

                uint32_t bb[4][2];
                const uint32_t* bp =
                    xs + (wrow + offj) * XPW + cq * 8 + (lane & 3);
#pragma unroll
                for (int nt = 0; nt < 4; ++nt) {
                    bb[nt][0] = bp[nt * 8 * XPW];
                    bb[nt][1] = bp[nt * 8 * XPW + 4];
                }
#pragma unroll
                for (int m = 0; m < 2; ++m)
#pragma unroll
                    for (int nt = 0; nt < 4; ++nt)
                        asm volatile(
                            "mma.sync.aligned.m16n8k16.row.col.f32.f16.f16.f32 "
                            "{%0,%1,%2,%3}, {%4,%5,%6,%7}, {%8,%9}, {%0,%1,%2,%3};"
                            : "+f"(acc[m][nt][0]), "+f"(acc[m][nt][1]),
                              "+f"(acc[m][nt][2]), "+f"(acc[m][nt][3])
                            : "r"(wf[m].x), "r"(wf[m].y),
                              "r"(wf[m].z), "r"(wf[m].w),
                              "r"(bb[nt][0]), "r"(bb[nt][1]));
            }
        }

        // ---- epilogue: +bias, STG.64 per C-fragment pair ----
        const int b  = tile >> 8;
        const int t0 = (tile & 255) << 8;
        float* ob = out + (size_t)b * NO * T_LEN + t0 + tg * 32 + 2 * (lane & 3);
#pragma unroll
        for (int m = 0; m < 2; ++m) {
            int oA = oA0 + m * 16;
#pragma unroll
            for (int nt = 0; nt < 4; ++nt) {
                float2 v0 = make_float2(acc[m][nt][0] + bv[m][0],
                                        acc[m][nt][1] + bv[m][0]);
                float2 v1 = make_float2(acc[m][nt][2] + bv[m][1],
                                        acc[m][nt][3] + bv[m][1]);
                *(float2*)(ob + (size_t)oA * T_LEN + nt * 8) = v0;
                *(float2*)(ob + (size_t)(oA + 8) * T_LEN + nt * 8) = v1;
            }
        }
    }
}

extern "C" void kernel_launch(void* const* d_in, const int* in_sizes, int n_in,
                              void* d_out, int out_size) {
    const float* x    = (const float*)d_in[0];
    const float* w    = (const float*)d_in[1];
    const float* bias = (const float*)d_in[2];
    float* out = (float*)d_out;

    zero_pads<<<(NB*64*32 + 255) / 256, 256>>>();
    conv_x<<<NB * 256, 256>>>(x);
    prep_w<<<(NCHUNK * 128 + 255) / 256, 256>>>(w);

    cudaFuncSetAttribute(taconv_mma,
                         cudaFuncAttributeMaxDynamicSharedMemorySize, SMTOT);
    taconv_mma<<<GRID, 512, SMTOT>>>(bias, out);
}